// round 8
// baseline (speedup 1.0000x reference)
#include <cuda_runtime.h>

// RoPE, minimal-dispatch single wave: 148 CTAs (1/SM) x 512 threads.
// Each thread owns up to 7 float4 elements (2 rotation pairs each) with ALL
// loads front-batched (MLP ~14) to cover DRAM/L2 latency in one shot.
// MUFU trig + exact 2-term Cody-Waite reduction; freq table compile-time.

#define PAIRS 32
#define TPB 512
#define GRID 148                 // one CTA per SM, single perfectly-even wave
#define ITERS 7                  // ceil(524288 / (148*512)) = 7

#define INV_2PI 0.15915493667125702f
#define TWO_PI_C1 6.28125f
#define TWO_PI_C2 1.9353071795864769e-3f
#define RND_MAGIC 12582912.0f

// 10^(-j/8), j = 0..31 (double literals -> correctly-rounded fp32)
__constant__ float c_freq[PAIRS] = {
    1.0f,
    (float)0.7498942093324559,   (float)0.5623413251903491,
    (float)0.4216965034285822,   (float)0.31622776601683794,
    (float)0.23713737056616552,  (float)0.17782794100389228,
    (float)0.13335214321633237,  (float)0.1,
    (float)0.07498942093324559,  (float)0.05623413251903491,
    (float)0.04216965034285822,  (float)0.031622776601683794,
    (float)0.023713737056616552, (float)0.017782794100389228,
    (float)0.013335214321633237, (float)0.01,
    (float)0.007498942093324559, (float)0.005623413251903491,
    (float)0.004216965034285822, (float)0.0031622776601683794,
    (float)0.0023713737056616552,(float)0.0017782794100389228,
    (float)0.0013335214321633237,(float)0.001,
    (float)0.0007498942093324559,(float)0.0005623413251903491,
    (float)0.0004216965034285822,(float)0.00031622776601683794,
    (float)0.00023713737056616552,(float)0.00017782794100389228,
    (float)0.00013335214321633237
};

__device__ __forceinline__ void fast_sincos(float ang, float& s, float& c) {
    float t = __fmaf_rn(ang, INV_2PI, RND_MAGIC);
    float k = t - RND_MAGIC;
    float r = __fmaf_rn(k, -TWO_PI_C1, ang);
    r = __fmaf_rn(k, -TWO_PI_C2, r);
    s = __sinf(r);
    c = __cosf(r);
}

__device__ __forceinline__ float4 rope_one(float4 xv, int g, float fp) {
    int q = (g & 15) << 1;               // first pair index of this float4
    float ang0 = __fmul_rn(fp, c_freq[q]);
    float ang1 = __fmul_rn(fp, c_freq[q + 1]);
    float s0, c0, s1, c1;
    fast_sincos(ang0, s0, c0);
    fast_sincos(ang1, s1, c1);
    float4 ov;
    ov.x = c0 * xv.x - s0 * xv.y;
    ov.y = s0 * xv.x + c0 * xv.y;
    ov.z = c1 * xv.z - s1 * xv.w;
    ov.w = s1 * xv.z + c1 * xv.w;
    return ov;
}

__global__ void __launch_bounds__(TPB) rope_1wave_kernel(
    const float4* __restrict__ x4,
    const int* __restrict__ pos,
    float4* __restrict__ o4,
    int n_f4)
{
    const int stride = GRID * TPB;       // 75776
    int tid = blockIdx.x * TPB + threadIdx.x;

    int g[ITERS];
    bool valid[ITERS];
    int p[ITERS];
    float4 xv[ITERS];

#pragma unroll
    for (int i = 0; i < ITERS; i++) {
        g[i] = tid + i * stride;
        valid[i] = g[i] < n_f4;
    }
    // front-batch every load (pos first: broadcast-friendly, then x)
#pragma unroll
    for (int i = 0; i < ITERS; i++)
        if (valid[i]) p[i] = __ldg(&pos[g[i] >> 4]);
#pragma unroll
    for (int i = 0; i < ITERS; i++)
        if (valid[i]) xv[i] = __ldg(&x4[g[i]]);

#pragma unroll
    for (int i = 0; i < ITERS; i++)
        if (valid[i]) o4[g[i]] = rope_one(xv[i], g[i], (float)p[i]);
}

extern "C" void kernel_launch(void* const* d_in, const int* in_sizes, int n_in,
                              void* d_out, int out_size) {
    const float4* x4  = (const float4*)d_in[0];  // (4, 8192, 64) f32
    const int*    pos = (const int*)d_in[1];     // (4, 8192) i32
    // d_in[2] = rope_buffer — unused (trig recomputed on the fly)
    float4* o4 = (float4*)d_out;

    int n_tokens = in_sizes[1];                  // 32768
    int n_f4 = n_tokens * 16;                    // 524288

    rope_1wave_kernel<<<GRID, TPB>>>(x4, pos, o4, n_f4);
}